// round 14
// baseline (speedup 1.0000x reference)
#include <cuda_runtime.h>

#define D 256
#define BATCH 8
#define SEQ 1024
#define ROWS (BATCH*SEQ)
#define RT 32
#define GS 8            // positions per phi CTA; j split across 2 CTAs
#define JH 128          // j per phi CTA

typedef unsigned long long ull;

// Scratch (static device globals -- no allocation allowed)
__device__ float  g_MT[2][D*D];        // M transposed: MT[k][i] = M[i][k]
__device__ float4 g_tbl[2][D*D];       // tbl[l][j*256+i] = (P[i][j], 1/p, sin(2pi/p), 2cos(2pi/p))
__device__ float  g_xt[ROWS*D];        // post GEMM+LN activations
__device__ float  g_y[ROWS*D];         // layer-1 output

// ---- f32x2 helpers (sm_103a packed fp32 pipe) ------------------------------
__device__ __forceinline__ ull pk2(float a, float b) {
    ull r; asm("mov.b64 %0, {%1,%2};" : "=l"(r) : "f"(a), "f"(b)); return r;
}
__device__ __forceinline__ void upk2(float& lo, float& hi, ull v) {
    asm("mov.b64 {%0,%1}, %2;" : "=f"(lo), "=f"(hi) : "l"(v));
}
__device__ __forceinline__ void fma2(ull& d, ull a, ull b) {
    asm("fma.rn.f32x2 %0, %1, %2, %0;" : "+l"(d) : "l"(a), "l"(b));
}

// ---------------------------------------------------------------------------
// Prep 1: transpose M1/M2 -> g_MT
// ---------------------------------------------------------------------------
__global__ void prep_mt_kernel(const float* __restrict__ M1, const float* __restrict__ M2)
{
    __shared__ float tile[32][33];
    const float* src = (blockIdx.z == 0) ? M1 : M2;
    float* dst = g_MT[blockIdx.z];

    int x = blockIdx.x * 32 + threadIdx.x;
    int y = blockIdx.y * 32 + threadIdx.y;
    #pragma unroll
    for (int r = 0; r < 32; r += 8)
        tile[threadIdx.y + r][threadIdx.x] = src[(y + r) * D + x];
    __syncthreads();
    x = blockIdx.y * 32 + threadIdx.x;
    y = blockIdx.x * 32 + threadIdx.y;
    #pragma unroll
    for (int r = 0; r < 32; r += 8)
        dst[(y + r) * D + x] = tile[threadIdx.x][threadIdx.y + r];
}

// ---------------------------------------------------------------------------
// Prep 2: fused table: g_tbl[l][j*256+i] = (P[i][j], 1/p, sin(2pi/p), 2cos(2pi/p))
// p = i*256 + j + 2
// ---------------------------------------------------------------------------
__global__ void prep_tbl_kernel(const float* __restrict__ P1, const float* __restrict__ P2)
{
    __shared__ float tile[32][33];
    const float* src = (blockIdx.z == 0) ? P1 : P2;
    float4* dst = g_tbl[blockIdx.z];

    int x = blockIdx.x * 32 + threadIdx.x;   // col j of P
    int y = blockIdx.y * 32 + threadIdx.y;   // row i of P
    #pragma unroll
    for (int r = 0; r < 32; r += 8)
        tile[threadIdx.y + r][threadIdx.x] = src[(y + r) * D + x];
    __syncthreads();
    int i = blockIdx.y * 32 + threadIdx.x;   // output col = i
    #pragma unroll
    for (int r = 0; r < 32; r += 8) {
        int j = blockIdx.x * 32 + threadIdx.y + r;
        float p    = (float)(i * D + j + 2);      // exact in fp32 (< 2^24)
        float rinv = 1.0f / p;
        float sd   = sinpif(2.0f * rinv);         // sin(2*pi/p), ~1 ulp
        float k2   = 2.0f * cospif(2.0f * rinv);  // 2*cos(2*pi/p)
        dst[(j << 8) + i] = make_float4(tile[threadIdx.x][threadIdx.y + r], rinv, sd, k2);
    }
}

// ---------------------------------------------------------------------------
// Kernel A: g_xt = LayerNorm(X @ M^T) * g + b,  plus OUT_init = X (residual
// pre-store so phi can accumulate with atomics).
// grid = ROWS/RT, 256 threads. Thread tile = 4 adjacent cols x 8 rows.
// ---------------------------------------------------------------------------
__global__ __launch_bounds__(256, 2)
void gemm_ln_kernel(const float* __restrict__ Xext, int layer,
                    const float* __restrict__ gw, const float* __restrict__ bw,
                    float* __restrict__ outinit_ext)
{
    __shared__ float sm[256 * 36];   // phase 1/2: [k][r] stride 36; phase 3/4: [r][i]

    const float* X     = (layer == 0) ? Xext : g_y;
    float* OUTI        = (layer == 0) ? g_y  : outinit_ext;
    const float* MT = g_MT[layer];

    const int tid = threadIdx.x;
    const int rg  = tid >> 6;          // row group: rows 8*rg .. 8*rg+7
    const int c4  = tid & 63;          // column quad: cols 4*c4 .. 4*c4+3
    const int r0  = blockIdx.x * RT;

    for (int idx = tid; idx < RT * D; idx += 256) {
        int r = idx >> 8, k = idx & 255;
        sm[k * 36 + r] = X[(r0 + r) * D + k];
    }
    __syncthreads();

    ull acc[4][4];                     // [c][row-pair]
    #pragma unroll
    for (int c = 0; c < 4; c++)
        #pragma unroll
        for (int q = 0; q < 4; q++) acc[c][q] = 0ULL;

    const float4* M4 = (const float4*)MT;        // M4[k*64 + c4]
    const int rbase = rg * 8;

    #pragma unroll 4
    for (int k = 0; k < D; k++) {
        float4 m = __ldg(&M4[k * 64 + c4]);                      // LDG.128 coalesced
        const ulonglong2* xp = (const ulonglong2*)&sm[k * 36 + rbase];  // 16B aligned
        ulonglong2 v0 = xp[0];
        ulonglong2 v1 = xp[1];
        ull m0 = pk2(m.x, m.x), m1 = pk2(m.y, m.y);
        ull m2 = pk2(m.z, m.z), m3 = pk2(m.w, m.w);
        fma2(acc[0][0], v0.x, m0); fma2(acc[0][1], v0.y, m0);
        fma2(acc[0][2], v1.x, m0); fma2(acc[0][3], v1.y, m0);
        fma2(acc[1][0], v0.x, m1); fma2(acc[1][1], v0.y, m1);
        fma2(acc[1][2], v1.x, m1); fma2(acc[1][3], v1.y, m1);
        fma2(acc[2][0], v0.x, m2); fma2(acc[2][1], v0.y, m2);
        fma2(acc[2][2], v1.x, m2); fma2(acc[2][3], v1.y, m2);
        fma2(acc[3][0], v0.x, m3); fma2(acc[3][1], v0.y, m3);
        fma2(acc[3][2], v1.x, m3); fma2(acc[3][3], v1.y, m3);
    }
    __syncthreads();

    // scatter to [r][i] layout
    #pragma unroll
    for (int q = 0; q < 4; q++) {
        float lo0, hi0, lo1, hi1, lo2, hi2, lo3, hi3;
        upk2(lo0, hi0, acc[0][q]);
        upk2(lo1, hi1, acc[1][q]);
        upk2(lo2, hi2, acc[2][q]);
        upk2(lo3, hi3, acc[3][q]);
        ((float4*)&sm[(rbase + 2 * q)     * D])[c4] = make_float4(lo0, lo1, lo2, lo3);
        ((float4*)&sm[(rbase + 2 * q + 1) * D])[c4] = make_float4(hi0, hi1, hi2, hi3);
    }
    __syncthreads();

    const int w = tid >> 5, lane = tid & 31;
    for (int rr = w; rr < RT; rr += 8) {
        float s1 = 0.f, s2 = 0.f;
        float v[8];
        #pragma unroll
        for (int u = 0; u < 8; u++) {
            v[u] = sm[rr * D + u * 32 + lane];
            s1 += v[u];
            s2 = fmaf(v[u], v[u], s2);
        }
        #pragma unroll
        for (int o = 16; o > 0; o >>= 1) {
            s1 += __shfl_xor_sync(0xffffffffu, s1, o);
            s2 += __shfl_xor_sync(0xffffffffu, s2, o);
        }
        float mu   = s1 * (1.0f / D);
        float var  = s2 * (1.0f / D) - mu * mu;
        float rstd = rsqrtf(var + 1e-5f);
        int row = r0 + rr;
        #pragma unroll
        for (int u = 0; u < 8; u++) {
            int col = u * 32 + lane;
            g_xt[row * D + col] =
                (v[u] - mu) * rstd * __ldg(&gw[col]) + __ldg(&bw[col]);
            // residual pre-store: phi atomically accumulates on top
            OUTI[row * D + col] = __ldg(&X[row * D + col]);
        }
    }
}

// ---------------------------------------------------------------------------
// Kernel B: OUT[b,s,i] += sum_j xt[b,s,j]*P[i,j]*cos(2*pi*s/p(i,j))
// grid = (SEQ/GS, 2) = (128,2): 8 positions per CTA, j-range split in halves.
// Trig amortized over 8 positions: one __sincosf + angle-addition + 6x
// Chebyshev per (i,j). Partial sums combined via float atomicAdd (REDG) on
// the residual-pre-initialized OUT. xts layout [j][b*8+u], stride 72.
// ---------------------------------------------------------------------------
__global__ __launch_bounds__(256, 2)
void phi_kernel(float* __restrict__ outext, int layer)
{
    __shared__ float xts[JH * 72];   // [j][b*8+u] + pad, 36.9 KB

    const float4* TB = g_tbl[layer];
    float* OUT = (layer == 0) ? g_y : outext;

    const int s0    = blockIdx.x * GS;
    const int jbase = blockIdx.y * JH;
    const int tid   = threadIdx.x;

    // stage 64 rows (8b x 8u) x 128 j
    for (int idx = tid; idx < GS * BATCH * JH; idx += 256) {
        int row = idx >> 7;             // 0..63 = b*8 + u
        int j   = idx & 127;
        int b   = row >> 3;
        int u   = row & 7;
        xts[j * 72 + row] = g_xt[((b << 10) + s0 + u) * D + jbase + j];
    }
    __syncthreads();

    ull acc[BATCH][4];                  // [b][u-pair 0..3]
    #pragma unroll
    for (int b = 0; b < BATCH; b++)
        #pragma unroll
        for (int q = 0; q < 4; q++) acc[b][q] = 0ULL;

    const float TWO_PI = 6.283185307179586f;
    const float sf0 = (float)s0;
    const bool  gen = (tid < 32);       // warp 0: may need range reduction

    #pragma unroll 2
    for (int j = 0; j < JH; j++) {
        float4 tb = __ldg(&TB[((jbase + j) << 8) + tid]);  // (P, 1/p, sd, k2)
        float t0 = sf0 * tb.y;
        if (gen) t0 -= floorf(t0);                // warp-uniform
        float s0v, c0;
        __sincosf(t0 * TWO_PI, &s0v, &c0);
        float c1 = fmaf(0.5f * tb.w, c0, -(s0v * tb.z));   // cos(theta0 + d)
        ull w0 = pk2(c0 * tb.x, c1 * tb.x);
        float ca = fmaf(tb.w, c1, -c0);                    // Chebyshev c2..c7
        float cb = fmaf(tb.w, ca, -c1);
        ull w1 = pk2(ca * tb.x, cb * tb.x);
        float cc = fmaf(tb.w, cb, -ca);
        float cd2 = fmaf(tb.w, cc, -cb);
        ull w2 = pk2(cc * tb.x, cd2 * tb.x);
        float ce = fmaf(tb.w, cd2, -cc);
        float cf = fmaf(tb.w, ce, -cd2);
        ull w3 = pk2(ce * tb.x, cf * tb.x);

        const ulonglong2* xb = (const ulonglong2*)&xts[j * 72];  // 16B aligned
        #pragma unroll
        for (int b = 0; b < BATCH; b++) {
            ulonglong2 v0 = xb[b * 2];      // (u0,u1 | u2,u3)
            ulonglong2 v1 = xb[b * 2 + 1];  // (u4,u5 | u6,u7)
            fma2(acc[b][0], v0.x, w0);
            fma2(acc[b][1], v0.y, w1);
            fma2(acc[b][2], v1.x, w2);
            fma2(acc[b][3], v1.y, w3);
        }
    }

    #pragma unroll
    for (int b = 0; b < BATCH; b++) {
        #pragma unroll
        for (int q = 0; q < 4; q++) {
            float lo, hi; upk2(lo, hi, acc[b][q]);
            int off = ((b << 10) + s0 + 2 * q) * D + tid;
            atomicAdd(&OUT[off],     lo);
            atomicAdd(&OUT[off + D], hi);
        }
    }
}

// ---------------------------------------------------------------------------
extern "C" void kernel_launch(void* const* d_in, const int* in_sizes, int n_in,
                              void* d_out, int out_size)
{
    const float* seq = (const float*)d_in[0];
    const float* M1  = (const float*)d_in[1];
    const float* P1  = (const float*)d_in[2];
    const float* g1  = (const float*)d_in[3];
    const float* b1  = (const float*)d_in[4];
    const float* M2  = (const float*)d_in[5];
    const float* P2  = (const float*)d_in[6];
    const float* g2  = (const float*)d_in[7];
    const float* b2  = (const float*)d_in[8];
    float* out = (float*)d_out;

    prep_mt_kernel <<<dim3(8, 8, 2), dim3(32, 8)>>>(M1, M2);
    prep_tbl_kernel<<<dim3(8, 8, 2), dim3(32, 8)>>>(P1, P2);

    // layer 1: gemm+LN (also pre-stores residual into g_y), then phi accumulates
    gemm_ln_kernel<<<ROWS / RT, 256>>>(seq, 0, g1, b1, nullptr);
    phi_kernel<<<dim3(SEQ / GS, 2), 256>>>(nullptr, 0);

    // layer 2: gemm+LN (pre-stores residual into d_out), then phi accumulates
    gemm_ln_kernel<<<ROWS / RT, 256>>>(nullptr, 1, g2, b2, out);
    phi_kernel<<<dim3(SEQ / GS, 2), 256>>>(out, 1);
}

// round 15
// speedup vs baseline: 1.0607x; 1.0607x over previous
#include <cuda_runtime.h>

#define D 256
#define BATCH 8
#define SEQ 1024
#define ROWS (BATCH*SEQ)
#define RT 32
#define GS 8            // positions per phi CTA
#define JH 128          // j per phi CTA (j-range split across blockIdx.y = 2)

typedef unsigned long long ull;

// Scratch (static device globals -- no allocation allowed)
__device__ float  g_MT[2][D*D];        // M transposed: MT[k][i] = M[i][k]
__device__ float4 g_tbl[2][D*D];       // tbl[l][j*256+i] = (P[i][j], 1/p, sin(2pi/p), 2cos(2pi/p))
__device__ float  g_xt[ROWS*D];        // post GEMM+LN activations
__device__ float  g_y[ROWS*D];         // layer-1 output

// ---- f32x2 helpers (sm_103a packed fp32 pipe) ------------------------------
__device__ __forceinline__ ull pk2(float a, float b) {
    ull r; asm("mov.b64 %0, {%1,%2};" : "=l"(r) : "f"(a), "f"(b)); return r;
}
__device__ __forceinline__ void upk2(float& lo, float& hi, ull v) {
    asm("mov.b64 {%0,%1}, %2;" : "=f"(lo), "=f"(hi) : "l"(v));
}
__device__ __forceinline__ void fma2(ull& d, ull a, ull b) {
    asm("fma.rn.f32x2 %0, %1, %2, %0;" : "+l"(d) : "l"(a), "l"(b));
}

// ---------------------------------------------------------------------------
// Prep (merged): z=0,1 -> transpose M1/M2 into g_MT; z=2,3 -> build trig table
// g_tbl[l][j*256+i] = (P[i][j], 1/p, sin(2pi/p), 2cos(2pi/p)),  p = i*256+j+2
// ---------------------------------------------------------------------------
__global__ void prep_kernel(const float* __restrict__ M1, const float* __restrict__ M2,
                            const float* __restrict__ P1, const float* __restrict__ P2)
{
    __shared__ float tile[32][33];
    int z = blockIdx.z;
    const float* src = (z == 0) ? M1 : (z == 1) ? M2 : (z == 2) ? P1 : P2;

    int x = blockIdx.x * 32 + threadIdx.x;
    int y = blockIdx.y * 32 + threadIdx.y;
    #pragma unroll
    for (int r = 0; r < 32; r += 8)
        tile[threadIdx.y + r][threadIdx.x] = src[(y + r) * D + x];
    __syncthreads();

    if (z < 2) {
        float* dst = g_MT[z];
        int xo = blockIdx.y * 32 + threadIdx.x;
        int yo = blockIdx.x * 32 + threadIdx.y;
        #pragma unroll
        for (int r = 0; r < 32; r += 8)
            dst[(yo + r) * D + xo] = tile[threadIdx.x][threadIdx.y + r];
    } else {
        float4* dst = g_tbl[z - 2];
        int i = blockIdx.y * 32 + threadIdx.x;        // output col = i
        #pragma unroll
        for (int r = 0; r < 32; r += 8) {
            int j = blockIdx.x * 32 + threadIdx.y + r;
            float p    = (float)(i * D + j + 2);      // exact in fp32 (< 2^24)
            float rinv = 1.0f / p;
            float sd   = sinpif(2.0f * rinv);         // sin(2*pi/p), ~1 ulp
            float k2   = 2.0f * cospif(2.0f * rinv);  // 2*cos(2*pi/p)
            dst[(j << 8) + i] = make_float4(tile[threadIdx.x][threadIdx.y + r], rinv, sd, k2);
        }
    }
}

// ---------------------------------------------------------------------------
// Kernel A: g_xt = LayerNorm(X @ M^T) * g + b, AND OUTI = X (residual
// pre-store fused into the staging loop: value already in a register).
// grid = ROWS/RT, 256 threads. Thread tile = 4 adjacent cols x 8 rows.
// ---------------------------------------------------------------------------
__global__ __launch_bounds__(256, 2)
void gemm_ln_kernel(const float* __restrict__ Xext, int layer,
                    const float* __restrict__ gw, const float* __restrict__ bw,
                    float* __restrict__ outinit_ext)
{
    __shared__ float sm[256 * 36];   // phase 1/2: [k][r] stride 36; phase 3/4: [r][i]

    const float* X  = (layer == 0) ? Xext : g_y;
    float* OUTI     = (layer == 0) ? g_y  : outinit_ext;
    const float* MT = g_MT[layer];

    const int tid = threadIdx.x;
    const int rg  = tid >> 6;          // row group: rows 8*rg .. 8*rg+7
    const int c4  = tid & 63;          // column quad: cols 4*c4 .. 4*c4+3
    const int r0  = blockIdx.x * RT;

    // stage X into smem [k][r]; fused residual pre-store (coalesced both ways)
    for (int idx = tid; idx < RT * D; idx += 256) {
        int r = idx >> 8, k = idx & 255;
        float v = X[(r0 + r) * D + k];
        sm[k * 36 + r] = v;
        OUTI[(r0 + r) * D + k] = v;
    }
    __syncthreads();

    ull acc[4][4];                     // [c][row-pair]
    #pragma unroll
    for (int c = 0; c < 4; c++)
        #pragma unroll
        for (int q = 0; q < 4; q++) acc[c][q] = 0ULL;

    const float4* M4 = (const float4*)MT;        // M4[k*64 + c4]
    const int rbase = rg * 8;

    #pragma unroll 4
    for (int k = 0; k < D; k++) {
        float4 m = __ldg(&M4[k * 64 + c4]);                      // LDG.128 coalesced
        const ulonglong2* xp = (const ulonglong2*)&sm[k * 36 + rbase];  // 16B aligned
        ulonglong2 v0 = xp[0];
        ulonglong2 v1 = xp[1];
        ull m0 = pk2(m.x, m.x), m1 = pk2(m.y, m.y);
        ull m2 = pk2(m.z, m.z), m3 = pk2(m.w, m.w);
        fma2(acc[0][0], v0.x, m0); fma2(acc[0][1], v0.y, m0);
        fma2(acc[0][2], v1.x, m0); fma2(acc[0][3], v1.y, m0);
        fma2(acc[1][0], v0.x, m1); fma2(acc[1][1], v0.y, m1);
        fma2(acc[1][2], v1.x, m1); fma2(acc[1][3], v1.y, m1);
        fma2(acc[2][0], v0.x, m2); fma2(acc[2][1], v0.y, m2);
        fma2(acc[2][2], v1.x, m2); fma2(acc[2][3], v1.y, m2);
        fma2(acc[3][0], v0.x, m3); fma2(acc[3][1], v0.y, m3);
        fma2(acc[3][2], v1.x, m3); fma2(acc[3][3], v1.y, m3);
    }
    __syncthreads();

    // scatter to [r][i] layout
    #pragma unroll
    for (int q = 0; q < 4; q++) {
        float lo0, hi0, lo1, hi1, lo2, hi2, lo3, hi3;
        upk2(lo0, hi0, acc[0][q]);
        upk2(lo1, hi1, acc[1][q]);
        upk2(lo2, hi2, acc[2][q]);
        upk2(lo3, hi3, acc[3][q]);
        ((float4*)&sm[(rbase + 2 * q)     * D])[c4] = make_float4(lo0, lo1, lo2, lo3);
        ((float4*)&sm[(rbase + 2 * q + 1) * D])[c4] = make_float4(hi0, hi1, hi2, hi3);
    }
    __syncthreads();

    const int w = tid >> 5, lane = tid & 31;
    for (int rr = w; rr < RT; rr += 8) {
        float s1 = 0.f, s2 = 0.f;
        float v[8];
        #pragma unroll
        for (int u = 0; u < 8; u++) {
            v[u] = sm[rr * D + u * 32 + lane];
            s1 += v[u];
            s2 = fmaf(v[u], v[u], s2);
        }
        #pragma unroll
        for (int o = 16; o > 0; o >>= 1) {
            s1 += __shfl_xor_sync(0xffffffffu, s1, o);
            s2 += __shfl_xor_sync(0xffffffffu, s2, o);
        }
        float mu   = s1 * (1.0f / D);
        float var  = s2 * (1.0f / D) - mu * mu;
        float rstd = rsqrtf(var + 1e-5f);
        int row = r0 + rr;
        #pragma unroll
        for (int u = 0; u < 8; u++) {
            int col = u * 32 + lane;
            g_xt[row * D + col] =
                (v[u] - mu) * rstd * __ldg(&gw[col]) + __ldg(&bw[col]);
        }
    }
}

// ---------------------------------------------------------------------------
// Kernel B: OUT[b,s,i] += sum_j xt[b,s,j]*P[i,j]*cos(2*pi*s/p(i,j))
// grid = (SEQ/GS, 2) = (128,2): 8 positions per CTA, j-range split in halves
// (halves each CTA's table traffic). One __sincosf + angle-add + 6x Chebyshev
// per (i,j) serves 64 units. Pointer-bumped addressing; two-pass w application
// keeps live registers low. Partials combined via float atomicAdd (REDG) onto
// the residual-pre-initialized OUT. xts layout [j][b*8+u], stride 72.
// ---------------------------------------------------------------------------
__global__ __launch_bounds__(256, 2)
void phi_kernel(float* __restrict__ outext, int layer)
{
    __shared__ float xts[JH * 72];   // [j][b*8+u] + pad, 36 KB

    float* OUT = (layer == 0) ? g_y : outext;

    const int s0    = blockIdx.x * GS;
    const int jbase = blockIdx.y * JH;
    const int tid   = threadIdx.x;

    // stage 64 rows (8b x 8u) x 128 j (coalesced LDG; STS conflicts one-time)
    for (int idx = tid; idx < GS * BATCH * JH; idx += 256) {
        int row = idx >> 7;             // 0..63 = b*8 + u
        int j   = idx & 127;
        int b   = row >> 3;
        int u   = row & 7;
        xts[j * 72 + row] = g_xt[((b << 10) + s0 + u) * D + jbase + j];
    }
    __syncthreads();

    ull acc[BATCH][4];                  // [b][u-pair 0..3]
    #pragma unroll
    for (int b = 0; b < BATCH; b++)
        #pragma unroll
        for (int q = 0; q < 4; q++) acc[b][q] = 0ULL;

    const float TWO_PI = 6.283185307179586f;
    const float sf0 = (float)s0;
    const bool  gen = (tid < 32);       // warp 0: may need range reduction

    const float4* tbp = &g_tbl[layer][(jbase << 8) + tid];
    const float*  xp  = xts;

    #pragma unroll 2
    for (int j = 0; j < JH; j++) {
        float4 tb = __ldg(tbp);  tbp += 256;      // (P, 1/p, sd, k2)
        float t0 = sf0 * tb.y;
        if (gen) t0 -= floorf(t0);                // warp-uniform
        float s0v, c0;
        __sincosf(t0 * TWO_PI, &s0v, &c0);
        float c1 = fmaf(0.5f * tb.w, c0, -(s0v * tb.z));   // cos(theta0 + d)
        float c2 = fmaf(tb.w, c1, -c0);                    // Chebyshev c2..c7
        float c3 = fmaf(tb.w, c2, -c1);
        float c4 = fmaf(tb.w, c3, -c2);
        float c5 = fmaf(tb.w, c4, -c3);
        float c6 = fmaf(tb.w, c5, -c4);
        float c7 = fmaf(tb.w, c6, -c5);

        const ulonglong2* xb = (const ulonglong2*)xp;      // 16B aligned

        // pass A: positions 0..3
        {
            ull w0 = pk2(c0 * tb.x, c1 * tb.x);
            ull w1 = pk2(c2 * tb.x, c3 * tb.x);
            #pragma unroll
            for (int b = 0; b < BATCH; b++) {
                ulonglong2 v = xb[b * 2];          // units (u0,u1 | u2,u3)
                fma2(acc[b][0], v.x, w0);
                fma2(acc[b][1], v.y, w1);
            }
        }
        // pass B: positions 4..7
        {
            ull w2 = pk2(c4 * tb.x, c5 * tb.x);
            ull w3 = pk2(c6 * tb.x, c7 * tb.x);
            #pragma unroll
            for (int b = 0; b < BATCH; b++) {
                ulonglong2 v = xb[b * 2 + 1];      // units (u4,u5 | u6,u7)
                fma2(acc[b][2], v.x, w2);
                fma2(acc[b][3], v.y, w3);
            }
        }
        xp += 72;
    }

    #pragma unroll
    for (int b = 0; b < BATCH; b++) {
        #pragma unroll
        for (int q = 0; q < 4; q++) {
            float lo, hi; upk2(lo, hi, acc[b][q]);
            int off = ((b << 10) + s0 + 2 * q) * D + tid;
            atomicAdd(&OUT[off],     lo);
            atomicAdd(&OUT[off + D], hi);
        }
    }
}

// ---------------------------------------------------------------------------
extern "C" void kernel_launch(void* const* d_in, const int* in_sizes, int n_in,
                              void* d_out, int out_size)
{
    const float* seq = (const float*)d_in[0];
    const float* M1  = (const float*)d_in[1];
    const float* P1  = (const float*)d_in[2];
    const float* g1  = (const float*)d_in[3];
    const float* b1  = (const float*)d_in[4];
    const float* M2  = (const float*)d_in[5];
    const float* P2  = (const float*)d_in[6];
    const float* g2  = (const float*)d_in[7];
    const float* b2  = (const float*)d_in[8];
    float* out = (float*)d_out;

    prep_kernel<<<dim3(8, 8, 4), dim3(32, 8)>>>(M1, M2, P1, P2);

    // layer 1: gemm+LN pre-stores residual (seq) into g_y; phi accumulates
    gemm_ln_kernel<<<ROWS / RT, 256>>>(seq, 0, g1, b1, nullptr);
    phi_kernel<<<dim3(SEQ / GS, 2), 256>>>(nullptr, 0);

    // layer 2: gemm+LN pre-stores residual (g_y) into d_out; phi accumulates
    gemm_ln_kernel<<<ROWS / RT, 256>>>(nullptr, 1, g2, b2, out);
    phi_kernel<<<dim3(SEQ / GS, 2), 256>>>(out, 1);
}